// round 3
// baseline (speedup 1.0000x reference)
#include <cuda_runtime.h>
#include <math.h>

#define NN 50000
#define FF 128
#define CC 512
#define EE 800000
#define HH 256

#define OFF_ADJ   (CC*FF)
#define OFF_BATCH (OFF_ADJ + CC*CC)
#define OFF_S     (OFF_BATCH + CC)

// ---------------- scratch ----------------------------------------------------
__device__ __align__(16) float g_h[(size_t)NN * HH];   // 256-wide buffer
__device__ __align__(16) float g_z[(size_t)NN * HH];   // 256-wide buffer
__device__ __align__(16) float g_l[(size_t)NN * CC];   // 512-wide logits
__device__ float g_inv[NN];
__device__ int   g_deg[NN];
__device__ int   g_off[NN + 1];
__device__ int   g_cur[NN];
__device__ int   g_csr_src[EE];
__device__ float g_csr_cf[EE];
__device__ int   g_cluster[NN];
__device__ float g_hs[NN];
__device__ int   g_sdeg[NN];
__device__ float g_invs[NN];
__device__ float g_sagg[NN];
__device__ float g_score[NN];
__device__ int   g_icnt[CC];
__device__ int   g_segkey[CC];
__device__ int   g_segidx[CC];
__device__ int   g_bsum[256];
__device__ int   g_bpref[256];

__device__ __forceinline__ int fkey(float f) {
    int b = __float_as_int(f);
    return b < 0 ? (b ^ 0x7FFFFFFF) : b;
}
__device__ __forceinline__ float fdec(int k) {
    return __int_as_float(k < 0 ? (k ^ 0x7FFFFFFF) : k);
}

// ---------------- init / degree ----------------------------------------------
__global__ void k_init(float* out) {
    int i = blockIdx.x * blockDim.x + threadIdx.x;
    int stride = gridDim.x * blockDim.x;
    for (int j = i; j < NN; j += stride) { g_deg[j] = 0; g_sdeg[j] = 0; g_sagg[j] = 0.f; }
    for (int j = i; j < CC; j += stride) {
        g_icnt[j] = 0; g_segkey[j] = (int)0x80000000; g_segidx[j] = NN;
        out[OFF_BATCH + j] = 0.f;
    }
    for (int j = i; j < CC * CC; j += stride) out[OFF_ADJ + j] = 0.f;
}

__global__ void k_deg(const int* __restrict__ ei) {
    int e = blockIdx.x * blockDim.x + threadIdx.x;
    if (e < EE) atomicAdd(&g_deg[ei[EE + e]], 1);
}

__global__ void k_inv() {
    int i = blockIdx.x * blockDim.x + threadIdx.x;
    if (i < NN) g_inv[i] = rsqrtf((float)g_deg[i] + 1.0f);
}

// ---------------- SGEMM 128x128x8, double-buffered, 8x8 micro ----------------
// Cm[M,Nc] = A[M,K] @ B[K,Nc] (+bias, relu if epi)
#define GEMM_ROW(cm, av)                              \
    cm[0].x = fmaf(av, b0.x, cm[0].x);                \
    cm[0].y = fmaf(av, b0.y, cm[0].y);                \
    cm[0].z = fmaf(av, b0.z, cm[0].z);                \
    cm[0].w = fmaf(av, b0.w, cm[0].w);                \
    cm[1].x = fmaf(av, b1.x, cm[1].x);                \
    cm[1].y = fmaf(av, b1.y, cm[1].y);                \
    cm[1].z = fmaf(av, b1.z, cm[1].z);                \
    cm[1].w = fmaf(av, b1.w, cm[1].w);

#define GEMM_COMPUTE(BUF)                                              \
    _Pragma("unroll")                                                  \
    for (int kk = 0; kk < 8; kk++) {                                   \
        float4 a0 = *(const float4*)&As[BUF][kk][ty * 8];              \
        float4 a1 = *(const float4*)&As[BUF][kk][ty * 8 + 4];          \
        float4 b0 = *(const float4*)&Bs[BUF][kk][tx * 8];              \
        float4 b1 = *(const float4*)&Bs[BUF][kk][tx * 8 + 4];          \
        GEMM_ROW(c[0], a0.x) GEMM_ROW(c[1], a0.y)                      \
        GEMM_ROW(c[2], a0.z) GEMM_ROW(c[3], a0.w)                      \
        GEMM_ROW(c[4], a1.x) GEMM_ROW(c[5], a1.y)                      \
        GEMM_ROW(c[6], a1.z) GEMM_ROW(c[7], a1.w)                      \
    }

__global__ void __launch_bounds__(256) k_gemm(const float* __restrict__ A,
                                              const float* __restrict__ B,
                                              const float* __restrict__ bias,
                                              float* __restrict__ Cm,
                                              int M, int K, int Nc, int epi) {
    __shared__ float As[2][8][128];
    __shared__ float Bs[2][8][128];
    const int tid = threadIdx.x;
    const int tx = tid & 15;
    const int ty = tid >> 4;
    const int rowBase = blockIdx.y * 128;
    const int colBase = blockIdx.x * 128;
    const int ar = tid >> 1;
    const int ac4 = (tid & 1) * 4;
    const int br = tid >> 5;
    const int bc4 = (tid & 31) * 4;
    const int gr = rowBase + ar;
    const bool aok = gr < M;
    const float* Aptr = A + (size_t)gr * K + ac4;
    const float* Bptr = B + (size_t)br * Nc + colBase + bc4;

    float4 c[8][2];
#pragma unroll
    for (int m = 0; m < 8; m++) {
        c[m][0] = make_float4(0.f, 0.f, 0.f, 0.f);
        c[m][1] = make_float4(0.f, 0.f, 0.f, 0.f);
    }

    // prologue: tile 0 -> buf 0
    {
        float4 va = aok ? *(const float4*)Aptr : make_float4(0.f, 0.f, 0.f, 0.f);
        float4 vb = *(const float4*)Bptr;
        As[0][ac4 + 0][ar] = va.x; As[0][ac4 + 1][ar] = va.y;
        As[0][ac4 + 2][ar] = va.z; As[0][ac4 + 3][ar] = va.w;
        *(float4*)&Bs[0][br][bc4] = vb;
    }
    __syncthreads();

    int buf = 0;
    for (int k0 = 8; k0 < K; k0 += 8) {
        float4 va = aok ? *(const float4*)(Aptr + k0) : make_float4(0.f, 0.f, 0.f, 0.f);
        float4 vb = *(const float4*)(Bptr + (size_t)k0 * Nc);
        GEMM_COMPUTE(buf)
        int nb = buf ^ 1;
        As[nb][ac4 + 0][ar] = va.x; As[nb][ac4 + 1][ar] = va.y;
        As[nb][ac4 + 2][ar] = va.z; As[nb][ac4 + 3][ar] = va.w;
        *(float4*)&Bs[nb][br][bc4] = vb;
        __syncthreads();
        buf = nb;
    }
    GEMM_COMPUTE(buf)

    float4 bb0 = make_float4(0.f, 0.f, 0.f, 0.f);
    float4 bb1 = make_float4(0.f, 0.f, 0.f, 0.f);
    if (epi) {
        bb0 = *(const float4*)(bias + colBase + tx * 8);
        bb1 = *(const float4*)(bias + colBase + tx * 8 + 4);
    }
#pragma unroll
    for (int m = 0; m < 8; m++) {
        int orow = rowBase + ty * 8 + m;
        if (orow < M) {
            float4 v0 = c[m][0], v1 = c[m][1];
            v0.x += bb0.x; v0.y += bb0.y; v0.z += bb0.z; v0.w += bb0.w;
            v1.x += bb1.x; v1.y += bb1.y; v1.z += bb1.z; v1.w += bb1.w;
            if (epi) {
                v0.x = fmaxf(v0.x, 0.f); v0.y = fmaxf(v0.y, 0.f);
                v0.z = fmaxf(v0.z, 0.f); v0.w = fmaxf(v0.w, 0.f);
                v1.x = fmaxf(v1.x, 0.f); v1.y = fmaxf(v1.y, 0.f);
                v1.z = fmaxf(v1.z, 0.f); v1.w = fmaxf(v1.w, 0.f);
            }
            *(float4*)(Cm + (size_t)orow * Nc + colBase + tx * 8) = v0;
            *(float4*)(Cm + (size_t)orow * Nc + colBase + tx * 8 + 4) = v1;
        }
    }
}

// ---------------- scan (3 phases) --------------------------------------------
__global__ void __launch_bounds__(256) k_scan1() {
    __shared__ int s[256];
    int t = threadIdx.x;
    int i = blockIdx.x * 256 + t;
    int v = (i < NN) ? g_deg[i] : 0;
    s[t] = v;
    __syncthreads();
    for (int off = 1; off < 256; off <<= 1) {
        int u = (t >= off) ? s[t - off] : 0;
        __syncthreads();
        s[t] += u;
        __syncthreads();
    }
    if (i < NN) g_off[i] = s[t] - v;
    if (t == 255) g_bsum[blockIdx.x] = s[255];
}
__global__ void __launch_bounds__(256) k_scan2(int nblocks) {
    __shared__ int s[256];
    int t = threadIdx.x;
    int v = (t < nblocks) ? g_bsum[t] : 0;
    s[t] = v;
    __syncthreads();
    for (int off = 1; off < 256; off <<= 1) {
        int u = (t >= off) ? s[t - off] : 0;
        __syncthreads();
        s[t] += u;
        __syncthreads();
    }
    g_bpref[t] = s[t] - v;
    if (t == 255) g_off[NN] = s[255];
}
__global__ void __launch_bounds__(256) k_scan3() {
    int i = blockIdx.x * 256 + threadIdx.x;
    if (i < NN) {
        int o = g_off[i] + g_bpref[blockIdx.x];
        g_off[i] = o;
        g_cur[i] = o;
    }
}

__global__ void k_fill(const int* __restrict__ ei) {
    int e = blockIdx.x * blockDim.x + threadIdx.x;
    if (e >= EE) return;
    int s = ei[e], d = ei[EE + e];
    int p = atomicAdd(&g_cur[d], 1);
    g_csr_src[p] = s;
    g_csr_cf[p] = g_inv[s] * g_inv[d];
}

// ---------------- aggregation (float4, warp-group per node) ------------------
// z[i,:] = [relu]( inv(i)^2*h[i,:] + sum cf(e)*h[src,:] [+ bias] )
template <int D, bool EPI>
__global__ void __launch_bounds__(128) k_aggv(const float* __restrict__ h,
                                              float* __restrict__ z,
                                              const float* __restrict__ bias) {
    constexpr int LPN = D / 4;           // lanes per node
    constexpr int NPB = 128 / LPN;       // nodes per block
    int sub = threadIdx.x / LPN;
    int lane = threadIdx.x % LPN;
    int i = blockIdx.x * NPB + sub;
    if (i >= NN) return;

    const float4* h4 = (const float4*)h;
    int beg = g_off[i], end = g_off[i + 1];
    float inv = g_inv[i];
    float self = inv * inv;
    float4 hv = __ldg(h4 + (size_t)i * LPN + lane);
    float4 acc = make_float4(self * hv.x, self * hv.y, self * hv.z, self * hv.w);

    int j = beg;
    for (; j + 4 <= end; j += 4) {
        int s0 = __ldg(g_csr_src + j + 0);
        int s1 = __ldg(g_csr_src + j + 1);
        int s2 = __ldg(g_csr_src + j + 2);
        int s3 = __ldg(g_csr_src + j + 3);
        float c0 = __ldg(g_csr_cf + j + 0);
        float c1 = __ldg(g_csr_cf + j + 1);
        float c2 = __ldg(g_csr_cf + j + 2);
        float c3 = __ldg(g_csr_cf + j + 3);
        float4 v0 = __ldg(h4 + (size_t)s0 * LPN + lane);
        float4 v1 = __ldg(h4 + (size_t)s1 * LPN + lane);
        float4 v2 = __ldg(h4 + (size_t)s2 * LPN + lane);
        float4 v3 = __ldg(h4 + (size_t)s3 * LPN + lane);
        acc.x = fmaf(c0, v0.x, acc.x); acc.y = fmaf(c0, v0.y, acc.y);
        acc.z = fmaf(c0, v0.z, acc.z); acc.w = fmaf(c0, v0.w, acc.w);
        acc.x = fmaf(c1, v1.x, acc.x); acc.y = fmaf(c1, v1.y, acc.y);
        acc.z = fmaf(c1, v1.z, acc.z); acc.w = fmaf(c1, v1.w, acc.w);
        acc.x = fmaf(c2, v2.x, acc.x); acc.y = fmaf(c2, v2.y, acc.y);
        acc.z = fmaf(c2, v2.z, acc.z); acc.w = fmaf(c2, v2.w, acc.w);
        acc.x = fmaf(c3, v3.x, acc.x); acc.y = fmaf(c3, v3.y, acc.y);
        acc.z = fmaf(c3, v3.z, acc.z); acc.w = fmaf(c3, v3.w, acc.w);
    }
    for (; j < end; j++) {
        int s0 = __ldg(g_csr_src + j);
        float c0 = __ldg(g_csr_cf + j);
        float4 v0 = __ldg(h4 + (size_t)s0 * LPN + lane);
        acc.x = fmaf(c0, v0.x, acc.x); acc.y = fmaf(c0, v0.y, acc.y);
        acc.z = fmaf(c0, v0.z, acc.z); acc.w = fmaf(c0, v0.w, acc.w);
    }
    if (EPI) {
        float4 bb = __ldg((const float4*)bias + lane);
        acc.x = fmaxf(acc.x + bb.x, 0.f);
        acc.y = fmaxf(acc.y + bb.y, 0.f);
        acc.z = fmaxf(acc.z + bb.z, 0.f);
        acc.w = fmaxf(acc.w + bb.w, 0.f);
    }
    ((float4*)z)[(size_t)i * LPN + lane] = acc;
}

// ---------------- softmax + argmax (first-max tie rule) ----------------------
__global__ void __launch_bounds__(256) k_softmax(const float* __restrict__ logits,
                                                 float* __restrict__ S) {
    int i = blockIdx.x;
    int t = threadIdx.x;
    const float* row = logits + (size_t)i * CC;
    float v0 = row[t], v1 = row[t + 256];
    float bv = v0; int bi = t;
    if (v1 > bv) { bv = v1; bi = t + 256; }

    __shared__ float sv[256];
    __shared__ int   si[256];
    sv[t] = bv; si[t] = bi;
    __syncthreads();
    for (int s = 128; s > 0; s >>= 1) {
        if (t < s) {
            float ov = sv[t + s]; int oi = si[t + s];
            if (ov > sv[t] || (ov == sv[t] && oi < si[t])) { sv[t] = ov; si[t] = oi; }
        }
        __syncthreads();
    }
    float m = sv[0];
    if (t == 0) g_cluster[i] = si[0];
    __syncthreads();

    float e0 = expf(v0 - m), e1 = expf(v1 - m);
    sv[t] = e0 + e1;
    __syncthreads();
    for (int s = 128; s > 0; s >>= 1) {
        if (t < s) sv[t] += sv[t + s];
        __syncthreads();
    }
    float invsum = 1.0f / sv[0];
    S[(size_t)i * CC + t]       = e0 * invsum;
    S[(size_t)i * CC + t + 256] = e1 * invsum;
}

// ---------------- score layer -------------------------------------------------
__global__ void k_hs(const float* __restrict__ x, const float* __restrict__ Ws) {
    int g = blockIdx.x * blockDim.x + threadIdx.x;
    int w = g >> 5, lane = g & 31;
    if (w >= NN) return;
    float4 xv = __ldg((const float4*)x + (size_t)w * 32 + lane);
    float4 wv = __ldg((const float4*)Ws + lane);
    float s = xv.x * wv.x + xv.y * wv.y + xv.z * wv.z + xv.w * wv.w;
#pragma unroll
    for (int off = 16; off > 0; off >>= 1) s += __shfl_down_sync(0xFFFFFFFF, s, off);
    if (lane == 0) g_hs[w] = s;
}

__global__ void k_intradeg(const int* __restrict__ ei) {
    int e = blockIdx.x * blockDim.x + threadIdx.x;
    if (e >= EE) return;
    int s = ei[e], d = ei[EE + e];
    int cs = g_cluster[s], cd = g_cluster[d];
    if (cs == cd) {
        atomicAdd(&g_sdeg[d], 1);
        atomicAdd(&g_icnt[cs], 1);
    }
}

__global__ void k_invs() {
    int i = blockIdx.x * blockDim.x + threadIdx.x;
    if (i < NN) g_invs[i] = rsqrtf((float)g_sdeg[i] + 1.0f);
}

__global__ void k_sagg(const int* __restrict__ ei) {
    int e = blockIdx.x * blockDim.x + threadIdx.x;
    if (e >= EE) return;
    int s = ei[e], d = ei[EE + e];
    if (g_cluster[s] == g_cluster[d])
        atomicAdd(&g_sagg[d], g_invs[s] * g_invs[d] * g_hs[s]);
}

__global__ void k_score(const float* __restrict__ bs) {
    int i = blockIdx.x * blockDim.x + threadIdx.x;
    if (i >= NN) return;
    float inv = g_invs[i];
    float v = g_sagg[i] + inv * inv * g_hs[i] + bs[0];
    g_score[i] = tanhf(v);
}

__global__ void k_segmax() {
    int i = blockIdx.x * blockDim.x + threadIdx.x;
    if (i >= NN) return;
    atomicMax(&g_segkey[g_cluster[i]], fkey(g_score[i]));
}

__global__ void k_segidx() {
    int i = blockIdx.x * blockDim.x + threadIdx.x;
    if (i >= NN) return;
    int c = g_cluster[i];
    float mx = fdec(g_segkey[c]);
    if (g_score[i] >= mx) atomicMin(&g_segidx[c], i);
}

// ---------------- pooling + adjacency ----------------------------------------
__global__ void __launch_bounds__(128) k_pool(const float* __restrict__ x,
                                              float* __restrict__ out) {
    int c = blockIdx.x;
    bool ne = g_icnt[c] > 0;
    float alpha = ne ? fdec(g_segkey[c]) : 0.f;
    int idx = min(g_segidx[c], NN - 1);
    out[(size_t)c * FF + threadIdx.x] = x[(size_t)idx * FF + threadIdx.x] * alpha;
}

__global__ void k_adj(const int* __restrict__ ei, float* __restrict__ out) {
    int e = blockIdx.x * blockDim.x + threadIdx.x;
    if (e >= EE) return;
    int cs = g_cluster[ei[e]], cd = g_cluster[ei[EE + e]];
    if (cs != cd && g_icnt[cs] > 0 && g_icnt[cd] > 0)
        out[OFF_ADJ + (size_t)cs * CC + cd] = 1.0f;
}

// ---------------- launch ------------------------------------------------------
extern "C" void kernel_launch(void* const* d_in, const int* in_sizes, int n_in,
                              void* d_out, int out_size) {
    const float* x   = (const float*)d_in[0];
    const int*   ei  = (const int*)d_in[1];
    const float* W1  = (const float*)d_in[3];
    const float* b1  = (const float*)d_in[4];
    const float* W2  = (const float*)d_in[5];
    const float* b2  = (const float*)d_in[6];
    const float* W3  = (const float*)d_in[7];
    const float* b3  = (const float*)d_in[8];
    const float* Ws  = (const float*)d_in[9];
    const float* bs  = (const float*)d_in[10];
    float* out = (float*)d_out;

    const int EB = (EE + 255) / 256;
    const int NB = (NN + 255) / 256;

    // indices 0..3 fixed so ncu (-s capture @ launch 3) profiles gemm1
    k_init<<<512, 256>>>(out);                                      // 0
    k_deg<<<EB, 256>>>(ei);                                         // 1
    k_inv<<<NB, 256>>>();                                           // 2
    {                                                               // 3: h = x @ W1
        dim3 g(HH / 128, (NN + 127) / 128);
        k_gemm<<<g, 256>>>(x, W1, (const float*)0, g_h, NN, FF, HH, 0);
    }
    k_scan1<<<NB, 256>>>();
    k_scan2<<<1, 256>>>(NB);
    k_scan3<<<NB, 256>>>();
    k_fill<<<EB, 256>>>(ei);

    // layer 1: z1 = relu(Ahat @ h + b1)
    k_aggv<HH, true><<<(NN + 1) / 2, 128>>>(g_h, g_z, b1);
    // layer 2: z2 = Ahat @ z1 ; h2 = relu(z2 @ W2 + b2)
    k_aggv<HH, false><<<(NN + 1) / 2, 128>>>(g_z, g_h, (const float*)0);
    {
        dim3 g(HH / 128, (NN + 127) / 128);
        k_gemm<<<g, 256>>>(g_h, W2, b2, g_z, NN, HH, HH, 1);
    }
    // layer 3: z3 = Ahat @ h2 ; logits = relu(z3 @ W3 + b3)
    k_aggv<HH, false><<<(NN + 1) / 2, 128>>>(g_z, g_h, (const float*)0);
    {
        dim3 g(CC / 128, (NN + 127) / 128);
        k_gemm<<<g, 256>>>(g_h, W3, b3, g_l, NN, HH, CC, 1);
    }

    k_softmax<<<NN, 256>>>(g_l, out + OFF_S);

    k_hs<<<(NN * 32 + 255) / 256, 256>>>(x, Ws);
    k_intradeg<<<EB, 256>>>(ei);
    k_invs<<<NB, 256>>>();
    k_sagg<<<EB, 256>>>(ei);
    k_score<<<NB, 256>>>(bs);
    k_segmax<<<NB, 256>>>();
    k_segidx<<<NB, 256>>>();
    k_pool<<<CC, 128>>>(x, out);
    k_adj<<<EB, 256>>>(ei, out);

    (void)in_sizes; (void)n_in; (void)out_size;
}

// round 4
// speedup vs baseline: 1.1841x; 1.1841x over previous
#include <cuda_runtime.h>
#include <math.h>
#include <stdint.h>

#define NN 50000
#define FF 128
#define CC 512
#define EE 800000
#define HH 256

#define OFF_ADJ   (CC*FF)
#define OFF_BATCH (OFF_ADJ + CC*CC)
#define OFF_S     (OFF_BATCH + CC)

// ---------------- scratch ----------------------------------------------------
__device__ __align__(16) float g_h[(size_t)NN * HH];
__device__ __align__(16) float g_z[(size_t)NN * HH];
__device__ __align__(16) float g_l[(size_t)NN * CC];
__device__ float g_inv[NN];
__device__ int   g_deg[NN];
__device__ int   g_off[NN + 1];
__device__ int   g_cur[NN];
__device__ int   g_csr_src[EE];
__device__ float g_csr_cf[EE];
__device__ int   g_cluster[NN];
__device__ float g_hs[NN];
__device__ int   g_sdeg[NN];
__device__ float g_invs[NN];
__device__ float g_sagg[NN];
__device__ float g_score[NN];
__device__ int   g_icnt[CC];
__device__ int   g_segkey[CC];
__device__ int   g_segidx[CC];
__device__ int   g_bsum[256];
__device__ int   g_bpref[256];

__device__ __forceinline__ int fkey(float f) {
    int b = __float_as_int(f);
    return b < 0 ? (b ^ 0x7FFFFFFF) : b;
}
__device__ __forceinline__ float fdec(int k) {
    return __int_as_float(k < 0 ? (k ^ 0x7FFFFFFF) : k);
}

// ---------------- init / degree ----------------------------------------------
__global__ void k_init(float* out) {
    int i = blockIdx.x * blockDim.x + threadIdx.x;
    int stride = gridDim.x * blockDim.x;
    for (int j = i; j < NN; j += stride) { g_deg[j] = 0; g_sdeg[j] = 0; g_sagg[j] = 0.f; }
    for (int j = i; j < CC; j += stride) {
        g_icnt[j] = 0; g_segkey[j] = (int)0x80000000; g_segidx[j] = NN;
        out[OFF_BATCH + j] = 0.f;
    }
    for (int j = i; j < CC * CC; j += stride) out[OFF_ADJ + j] = 0.f;
}

__global__ void k_deg(const int* __restrict__ ei) {
    int e = blockIdx.x * blockDim.x + threadIdx.x;
    if (e < EE) atomicAdd(&g_deg[ei[EE + e]], 1);
}

__global__ void k_inv() {
    int i = blockIdx.x * blockDim.x + threadIdx.x;
    if (i < NN) g_inv[i] = rsqrtf((float)g_deg[i] + 1.0f);
}

// ---------------- scan (3 phases) --------------------------------------------
__global__ void __launch_bounds__(256) k_scan1() {
    __shared__ int s[256];
    int t = threadIdx.x;
    int i = blockIdx.x * 256 + t;
    int v = (i < NN) ? g_deg[i] : 0;
    s[t] = v;
    __syncthreads();
    for (int off = 1; off < 256; off <<= 1) {
        int u = (t >= off) ? s[t - off] : 0;
        __syncthreads();
        s[t] += u;
        __syncthreads();
    }
    if (i < NN) g_off[i] = s[t] - v;
    if (t == 255) g_bsum[blockIdx.x] = s[255];
}
__global__ void __launch_bounds__(256) k_scan2(int nblocks) {
    __shared__ int s[256];
    int t = threadIdx.x;
    int v = (t < nblocks) ? g_bsum[t] : 0;
    s[t] = v;
    __syncthreads();
    for (int off = 1; off < 256; off <<= 1) {
        int u = (t >= off) ? s[t - off] : 0;
        __syncthreads();
        s[t] += u;
        __syncthreads();
    }
    g_bpref[t] = s[t] - v;
    if (t == 255) g_off[NN] = s[255];
}
__global__ void __launch_bounds__(256) k_scan3() {
    int i = blockIdx.x * 256 + threadIdx.x;
    if (i < NN) {
        int o = g_off[i] + g_bpref[blockIdx.x];
        g_off[i] = o;
        g_cur[i] = o;
    }
}

__global__ void k_fill(const int* __restrict__ ei) {
    int e = blockIdx.x * blockDim.x + threadIdx.x;
    if (e >= EE) return;
    int s = ei[e], d = ei[EE + e];
    int p = atomicAdd(&g_cur[d], 1);
    g_csr_src[p] = s;
    g_csr_cf[p] = g_inv[s] * g_inv[d];
}

// ---------------- split-tf32 tensor-core GEMM --------------------------------
// Cm[M,Nc] = A[M,K] @ B[K,Nc] (+bias, relu if EPI). M arbitrary, K%8==0, Nc%128==0.
__device__ __forceinline__ uint32_t f2tf(float f) {
    uint32_t r;
    asm("cvt.rna.tf32.f32 %0, %1;" : "=r"(r) : "f"(f));
    return r;
}
__device__ __forceinline__ void mma_tf32(float4& d,
                                         uint32_t a0, uint32_t a1, uint32_t a2, uint32_t a3,
                                         uint32_t b0, uint32_t b1) {
    asm volatile("mma.sync.aligned.m16n8k8.row.col.f32.tf32.tf32.f32 "
                 "{%0,%1,%2,%3}, {%4,%5,%6,%7}, {%8,%9}, {%0,%1,%2,%3};"
                 : "+f"(d.x), "+f"(d.y), "+f"(d.z), "+f"(d.w)
                 : "r"(a0), "r"(a1), "r"(a2), "r"(a3), "r"(b0), "r"(b1));
}

#define TCSTRIDE 136

__global__ void __launch_bounds__(256) k_tcgemm(const float* __restrict__ A,
                                                const float* __restrict__ B,
                                                const float* __restrict__ bias,
                                                float* __restrict__ Cm,
                                                int M, int K, int Nc, int epi) {
    __shared__ uint32_t Ah[2][8][TCSTRIDE];
    __shared__ uint32_t Al[2][8][TCSTRIDE];
    __shared__ uint32_t Bh[2][8][TCSTRIDE];
    __shared__ uint32_t Bl[2][8][TCSTRIDE];

    const int tid = threadIdx.x;
    const int wid = tid >> 5;
    const int lane = tid & 31;
    const int q = lane >> 2;        // 0..7
    const int t4 = lane & 3;        // 0..3
    const int wm = wid & 3;         // 4 warps along M
    const int wn = wid >> 2;        // 2 warps along N
    const int m0 = wm * 32;
    const int n0 = wn * 64;

    const int rowBase = blockIdx.y * 128;
    const int colBase = blockIdx.x * 128;

    // loaders
    const int ar = tid >> 1;              // 0..127
    const int ac4 = (tid & 1) * 4;        // 0 or 4
    const int br = tid >> 5;              // 0..7
    const int bc4 = (tid & 31) * 4;       // 0..124
    const bool aok = (rowBase + ar) < M;
    const float* Aptr = A + (size_t)(rowBase + ar) * K + ac4;
    const float* Bptr = B + (size_t)br * Nc + colBase + bc4;

    float4 acc[2][8];
#pragma unroll
    for (int mi = 0; mi < 2; mi++)
#pragma unroll
        for (int ni = 0; ni < 8; ni++) acc[mi][ni] = make_float4(0.f, 0.f, 0.f, 0.f);

#define SPLIT_STORE(arrH, arrL, BUF, R, CBASE, V)                    \
    {                                                                \
        uint32_t h_ = f2tf(V);                                       \
        float lo_ = (V) - __uint_as_float(h_);                       \
        arrH[BUF][CBASE][R] = h_;                                    \
        arrL[BUF][CBASE][R] = f2tf(lo_);                             \
    }

#define LOAD_TILE(BUF, K0)                                                        \
    {                                                                             \
        float4 va = aok ? *(const float4*)(Aptr + (K0))                           \
                        : make_float4(0.f, 0.f, 0.f, 0.f);                        \
        float4 vb = *(const float4*)(Bptr + (size_t)(K0) * Nc);                   \
        SPLIT_STORE(Ah, Al, BUF, ar, ac4 + 0, va.x)                               \
        SPLIT_STORE(Ah, Al, BUF, ar, ac4 + 1, va.y)                               \
        SPLIT_STORE(Ah, Al, BUF, ar, ac4 + 2, va.z)                               \
        SPLIT_STORE(Ah, Al, BUF, ar, ac4 + 3, va.w)                               \
        SPLIT_STORE(Bh, Bl, BUF, bc4 + 0, br, vb.x)                               \
        SPLIT_STORE(Bh, Bl, BUF, bc4 + 1, br, vb.y)                               \
        SPLIT_STORE(Bh, Bl, BUF, bc4 + 2, br, vb.z)                               \
        SPLIT_STORE(Bh, Bl, BUF, bc4 + 3, br, vb.w)                               \
    }

#define COMPUTE_TILE(BUF)                                                          \
    {                                                                              \
        uint32_t ah[2][4], al[2][4];                                               \
        _Pragma("unroll")                                                          \
        for (int mi = 0; mi < 2; mi++) {                                           \
            int mrow = m0 + mi * 16;                                               \
            ah[mi][0] = Ah[BUF][t4][mrow + q];                                     \
            ah[mi][1] = Ah[BUF][t4][mrow + q + 8];                                 \
            ah[mi][2] = Ah[BUF][t4 + 4][mrow + q];                                 \
            ah[mi][3] = Ah[BUF][t4 + 4][mrow + q + 8];                             \
            al[mi][0] = Al[BUF][t4][mrow + q];                                     \
            al[mi][1] = Al[BUF][t4][mrow + q + 8];                                 \
            al[mi][2] = Al[BUF][t4 + 4][mrow + q];                                 \
            al[mi][3] = Al[BUF][t4 + 4][mrow + q + 8];                             \
        }                                                                          \
        _Pragma("unroll")                                                          \
        for (int ni = 0; ni < 8; ni++) {                                           \
            int ncol = n0 + ni * 8 + q;                                            \
            uint32_t bh0 = Bh[BUF][t4][ncol];                                      \
            uint32_t bh1 = Bh[BUF][t4 + 4][ncol];                                  \
            uint32_t bl0 = Bl[BUF][t4][ncol];                                      \
            uint32_t bl1 = Bl[BUF][t4 + 4][ncol];                                  \
            _Pragma("unroll")                                                      \
            for (int mi = 0; mi < 2; mi++) {                                       \
                mma_tf32(acc[mi][ni], ah[mi][0], ah[mi][1], ah[mi][2], ah[mi][3],  \
                         bh0, bh1);                                                \
                mma_tf32(acc[mi][ni], ah[mi][0], ah[mi][1], ah[mi][2], ah[mi][3],  \
                         bl0, bl1);                                                \
                mma_tf32(acc[mi][ni], al[mi][0], al[mi][1], al[mi][2], al[mi][3],  \
                         bh0, bh1);                                                \
            }                                                                      \
        }                                                                          \
    }

    // note: Bs stores use [col][row] to match frag access Bh[k][n]?  We store
    // Bh[BUF][bc4+i][br] -> that is [n][k]!  Fix: frags read Bh[t4][ncol] = [k][n].
    // So stores above must be Bh[BUF][br][bc4+i].  (handled below by remap)
#undef SPLIT_STORE
#define SPLIT_STORE(arrH, arrL, BUF, D0, D1, V)                      \
    {                                                                \
        uint32_t h_ = f2tf(V);                                       \
        float lo_ = (V) - __uint_as_float(h_);                       \
        arrH[BUF][D0][D1] = h_;                                      \
        arrL[BUF][D0][D1] = f2tf(lo_);                               \
    }
#undef LOAD_TILE
#define LOAD_TILE(BUF, K0)                                                        \
    {                                                                             \
        float4 va = aok ? *(const float4*)(Aptr + (K0))                           \
                        : make_float4(0.f, 0.f, 0.f, 0.f);                        \
        float4 vb = *(const float4*)(Bptr + (size_t)(K0) * Nc);                   \
        SPLIT_STORE(Ah, Al, BUF, ac4 + 0, ar, va.x)                               \
        SPLIT_STORE(Ah, Al, BUF, ac4 + 1, ar, va.y)                               \
        SPLIT_STORE(Ah, Al, BUF, ac4 + 2, ar, va.z)                               \
        SPLIT_STORE(Ah, Al, BUF, ac4 + 3, ar, va.w)                               \
        SPLIT_STORE(Bh, Bl, BUF, br, bc4 + 0, vb.x)                               \
        SPLIT_STORE(Bh, Bl, BUF, br, bc4 + 1, vb.y)                               \
        SPLIT_STORE(Bh, Bl, BUF, br, bc4 + 2, vb.z)                               \
        SPLIT_STORE(Bh, Bl, BUF, br, bc4 + 3, vb.w)                               \
    }

    LOAD_TILE(0, 0)
    __syncthreads();

    int buf = 0;
    for (int k0 = 8; k0 < K; k0 += 8) {
        COMPUTE_TILE(buf)
        LOAD_TILE(buf ^ 1, k0)
        __syncthreads();
        buf ^= 1;
    }
    COMPUTE_TILE(buf)

    // epilogue
#pragma unroll
    for (int mi = 0; mi < 2; mi++) {
#pragma unroll
        for (int ni = 0; ni < 8; ni++) {
            int col = colBase + n0 + ni * 8 + 2 * t4;
            float bb0 = 0.f, bb1 = 0.f;
            if (epi) { bb0 = bias[col]; bb1 = bias[col + 1]; }
            int r0 = rowBase + m0 + mi * 16 + q;
            int r1 = r0 + 8;
            float4 v = acc[mi][ni];
            float o0 = v.x + bb0, o1 = v.y + bb1, o2 = v.z + bb0, o3 = v.w + bb1;
            if (epi) {
                o0 = fmaxf(o0, 0.f); o1 = fmaxf(o1, 0.f);
                o2 = fmaxf(o2, 0.f); o3 = fmaxf(o3, 0.f);
            }
            if (r0 < M) *(float2*)(Cm + (size_t)r0 * Nc + col) = make_float2(o0, o1);
            if (r1 < M) *(float2*)(Cm + (size_t)r1 * Nc + col) = make_float2(o2, o3);
        }
    }
}

// ---------------- aggregation: warp per node, float4, 4-edge unroll ----------
template <int D, bool EPI>
__global__ void __launch_bounds__(256) k_aggw(const float* __restrict__ h,
                                              float* __restrict__ z,
                                              const float* __restrict__ bias) {
    constexpr int V = D / 128;          // float4 per lane
    int i = blockIdx.x * 8 + (threadIdx.x >> 5);
    if (i >= NN) return;
    int lane = threadIdx.x & 31;

    const float4* h4 = (const float4*)h;
    int beg = g_off[i], end = g_off[i + 1];
    float inv = g_inv[i];
    float self = inv * inv;
    float4 acc[V];
#pragma unroll
    for (int v = 0; v < V; v++) {
        float4 t = __ldg(h4 + (size_t)i * (D / 4) + lane + v * 32);
        acc[v] = make_float4(self * t.x, self * t.y, self * t.z, self * t.w);
    }

    int j = beg;
    for (; j + 4 <= end; j += 4) {
        int s0 = __ldg(g_csr_src + j + 0);
        int s1 = __ldg(g_csr_src + j + 1);
        int s2 = __ldg(g_csr_src + j + 2);
        int s3 = __ldg(g_csr_src + j + 3);
        float c0 = __ldg(g_csr_cf + j + 0);
        float c1 = __ldg(g_csr_cf + j + 1);
        float c2 = __ldg(g_csr_cf + j + 2);
        float c3 = __ldg(g_csr_cf + j + 3);
#pragma unroll
        for (int v = 0; v < V; v++) {
            float4 v0 = __ldg(h4 + (size_t)s0 * (D / 4) + lane + v * 32);
            float4 v1 = __ldg(h4 + (size_t)s1 * (D / 4) + lane + v * 32);
            float4 v2 = __ldg(h4 + (size_t)s2 * (D / 4) + lane + v * 32);
            float4 v3 = __ldg(h4 + (size_t)s3 * (D / 4) + lane + v * 32);
            acc[v].x = fmaf(c0, v0.x, acc[v].x); acc[v].y = fmaf(c0, v0.y, acc[v].y);
            acc[v].z = fmaf(c0, v0.z, acc[v].z); acc[v].w = fmaf(c0, v0.w, acc[v].w);
            acc[v].x = fmaf(c1, v1.x, acc[v].x); acc[v].y = fmaf(c1, v1.y, acc[v].y);
            acc[v].z = fmaf(c1, v1.z, acc[v].z); acc[v].w = fmaf(c1, v1.w, acc[v].w);
            acc[v].x = fmaf(c2, v2.x, acc[v].x); acc[v].y = fmaf(c2, v2.y, acc[v].y);
            acc[v].z = fmaf(c2, v2.z, acc[v].z); acc[v].w = fmaf(c2, v2.w, acc[v].w);
            acc[v].x = fmaf(c3, v3.x, acc[v].x); acc[v].y = fmaf(c3, v3.y, acc[v].y);
            acc[v].z = fmaf(c3, v3.z, acc[v].z); acc[v].w = fmaf(c3, v3.w, acc[v].w);
        }
    }
    for (; j < end; j++) {
        int s0 = __ldg(g_csr_src + j);
        float c0 = __ldg(g_csr_cf + j);
#pragma unroll
        for (int v = 0; v < V; v++) {
            float4 v0 = __ldg(h4 + (size_t)s0 * (D / 4) + lane + v * 32);
            acc[v].x = fmaf(c0, v0.x, acc[v].x); acc[v].y = fmaf(c0, v0.y, acc[v].y);
            acc[v].z = fmaf(c0, v0.z, acc[v].z); acc[v].w = fmaf(c0, v0.w, acc[v].w);
        }
    }
#pragma unroll
    for (int v = 0; v < V; v++) {
        if (EPI) {
            float4 bb = __ldg((const float4*)bias + lane + v * 32);
            acc[v].x = fmaxf(acc[v].x + bb.x, 0.f);
            acc[v].y = fmaxf(acc[v].y + bb.y, 0.f);
            acc[v].z = fmaxf(acc[v].z + bb.z, 0.f);
            acc[v].w = fmaxf(acc[v].w + bb.w, 0.f);
        }
        ((float4*)z)[(size_t)i * (D / 4) + lane + v * 32] = acc[v];
    }
}

// ---------------- softmax + argmax (first-max tie rule) ----------------------
__global__ void __launch_bounds__(256) k_softmax(const float* __restrict__ logits,
                                                 float* __restrict__ S) {
    int i = blockIdx.x;
    int t = threadIdx.x;
    const float* row = logits + (size_t)i * CC;
    float v0 = row[t], v1 = row[t + 256];
    float bv = v0; int bi = t;
    if (v1 > bv) { bv = v1; bi = t + 256; }

    __shared__ float sv[256];
    __shared__ int   si[256];
    sv[t] = bv; si[t] = bi;
    __syncthreads();
    for (int s = 128; s > 0; s >>= 1) {
        if (t < s) {
            float ov = sv[t + s]; int oi = si[t + s];
            if (ov > sv[t] || (ov == sv[t] && oi < si[t])) { sv[t] = ov; si[t] = oi; }
        }
        __syncthreads();
    }
    float m = sv[0];
    if (t == 0) g_cluster[i] = si[0];
    __syncthreads();

    float e0 = expf(v0 - m), e1 = expf(v1 - m);
    sv[t] = e0 + e1;
    __syncthreads();
    for (int s = 128; s > 0; s >>= 1) {
        if (t < s) sv[t] += sv[t + s];
        __syncthreads();
    }
    float invsum = 1.0f / sv[0];
    S[(size_t)i * CC + t]       = e0 * invsum;
    S[(size_t)i * CC + t + 256] = e1 * invsum;
}

// ---------------- score layer -------------------------------------------------
__global__ void k_hs(const float* __restrict__ x, const float* __restrict__ Ws) {
    int g = blockIdx.x * blockDim.x + threadIdx.x;
    int w = g >> 5, lane = g & 31;
    if (w >= NN) return;
    float4 xv = __ldg((const float4*)x + (size_t)w * 32 + lane);
    float4 wv = __ldg((const float4*)Ws + lane);
    float s = xv.x * wv.x + xv.y * wv.y + xv.z * wv.z + xv.w * wv.w;
#pragma unroll
    for (int off = 16; off > 0; off >>= 1) s += __shfl_down_sync(0xFFFFFFFF, s, off);
    if (lane == 0) g_hs[w] = s;
}

__global__ void k_intradeg(const int* __restrict__ ei) {
    int e = blockIdx.x * blockDim.x + threadIdx.x;
    if (e >= EE) return;
    int s = ei[e], d = ei[EE + e];
    int cs = g_cluster[s], cd = g_cluster[d];
    if (cs == cd) {
        atomicAdd(&g_sdeg[d], 1);
        atomicAdd(&g_icnt[cs], 1);
    }
}

__global__ void k_invs() {
    int i = blockIdx.x * blockDim.x + threadIdx.x;
    if (i < NN) g_invs[i] = rsqrtf((float)g_sdeg[i] + 1.0f);
}

__global__ void k_sagg(const int* __restrict__ ei) {
    int e = blockIdx.x * blockDim.x + threadIdx.x;
    if (e >= EE) return;
    int s = ei[e], d = ei[EE + e];
    if (g_cluster[s] == g_cluster[d])
        atomicAdd(&g_sagg[d], g_invs[s] * g_invs[d] * g_hs[s]);
}

__global__ void k_score(const float* __restrict__ bs) {
    int i = blockIdx.x * blockDim.x + threadIdx.x;
    if (i >= NN) return;
    float inv = g_invs[i];
    float v = g_sagg[i] + inv * inv * g_hs[i] + bs[0];
    g_score[i] = tanhf(v);
}

__global__ void k_segmax() {
    int i = blockIdx.x * blockDim.x + threadIdx.x;
    if (i >= NN) return;
    atomicMax(&g_segkey[g_cluster[i]], fkey(g_score[i]));
}

__global__ void k_segidx() {
    int i = blockIdx.x * blockDim.x + threadIdx.x;
    if (i >= NN) return;
    int c = g_cluster[i];
    float mx = fdec(g_segkey[c]);
    if (g_score[i] >= mx) atomicMin(&g_segidx[c], i);
}

// ---------------- pooling + adjacency ----------------------------------------
__global__ void __launch_bounds__(128) k_pool(const float* __restrict__ x,
                                              float* __restrict__ out) {
    int c = blockIdx.x;
    bool ne = g_icnt[c] > 0;
    float alpha = ne ? fdec(g_segkey[c]) : 0.f;
    int idx = min(g_segidx[c], NN - 1);
    out[(size_t)c * FF + threadIdx.x] = x[(size_t)idx * FF + threadIdx.x] * alpha;
}

__global__ void k_adj(const int* __restrict__ ei, float* __restrict__ out) {
    int e = blockIdx.x * blockDim.x + threadIdx.x;
    if (e >= EE) return;
    int cs = g_cluster[ei[e]], cd = g_cluster[ei[EE + e]];
    if (cs != cd && g_icnt[cs] > 0 && g_icnt[cd] > 0)
        out[OFF_ADJ + (size_t)cs * CC + cd] = 1.0f;
}

// ---------------- launch ------------------------------------------------------
extern "C" void kernel_launch(void* const* d_in, const int* in_sizes, int n_in,
                              void* d_out, int out_size) {
    const float* x   = (const float*)d_in[0];
    const int*   ei  = (const int*)d_in[1];
    const float* W1  = (const float*)d_in[3];
    const float* b1  = (const float*)d_in[4];
    const float* W2  = (const float*)d_in[5];
    const float* b2  = (const float*)d_in[6];
    const float* W3  = (const float*)d_in[7];
    const float* b3  = (const float*)d_in[8];
    const float* Ws  = (const float*)d_in[9];
    const float* bs  = (const float*)d_in[10];
    float* out = (float*)d_out;

    const int EB = (EE + 255) / 256;
    const int NB = (NN + 255) / 256;
    const int AB = (NN + 7) / 8;

    k_init<<<512, 256>>>(out);
    k_deg<<<EB, 256>>>(ei);
    k_inv<<<NB, 256>>>();
    k_scan1<<<NB, 256>>>();
    k_scan2<<<1, 256>>>(NB);
    k_scan3<<<NB, 256>>>();
    k_fill<<<EB, 256>>>(ei);

    // layer 1: z = Ahat @ x (128-wide); h = relu(z @ W1 + b1) (256)
    k_aggw<128, false><<<AB, 256>>>(x, g_z, (const float*)0);
    {
        dim3 g(HH / 128, (NN + 127) / 128);
        k_tcgemm<<<g, 256>>>(g_z, W1, b1, g_h, NN, FF, HH, 1);
    }
    // layer 2
    k_aggw<256, false><<<AB, 256>>>(g_h, g_z, (const float*)0);
    {
        dim3 g(HH / 128, (NN + 127) / 128);
        k_tcgemm<<<g, 256>>>(g_z, W2, b2, g_h, NN, HH, HH, 1);
    }
    // layer 3
    k_aggw<256, false><<<AB, 256>>>(g_h, g_z, (const float*)0);
    {
        dim3 g(CC / 128, (NN + 127) / 128);
        k_tcgemm<<<g, 256>>>(g_z, W3, b3, g_l, NN, HH, CC, 1);
    }

    k_softmax<<<NN, 256>>>(g_l, out + OFF_S);

    k_hs<<<(NN * 32 + 255) / 256, 256>>>(x, Ws);
    k_intradeg<<<EB, 256>>>(ei);
    k_invs<<<NB, 256>>>();
    k_sagg<<<EB, 256>>>(ei);
    k_score<<<NB, 256>>>(bs);
    k_segmax<<<NB, 256>>>();
    k_segidx<<<NB, 256>>>();
    k_pool<<<CC, 128>>>(x, out);
    k_adj<<<EB, 256>>>(ei, out);

    (void)in_sizes; (void)n_in; (void)out_size;
}